// round 16
// baseline (speedup 1.0000x reference)
#include <cuda_runtime.h>
#include <math.h>

#define NN 50000
#define NE 400000
#define TE 450000         // NE + NN self loops
#define HID 256
#define BATCHB 16

// ---------------- scratch ----------------
__device__ float g_h [(size_t)NN*HID];   // layer input / LN output
__device__ float g_hp[(size_t)NN*HID];   // h @ W (also feats buffer, N*192 < N*256)
__device__ float g_ssrc[NN*4];
__device__ float g_sdst[NN*4];
__device__ int   g_cnt[NN];
__device__ int   g_rowptr[NN+1];
__device__ int   g_cur[NN];
__device__ int   g_col[TE];
__device__ int   g_part[256];
__device__ float g_pool[BATCHB*HID];
__device__ int   g_bcnt[BATCHB];

// ---------------- feats + init (fused): rates computed per-block (bit-identical) ----------------
__global__ void feats_kernel(const float* __restrict__ x,
                             const float* __restrict__ remb,
                             const int*   __restrict__ rid) {
    __shared__ float rates[64];
    int tid = threadIdx.x;
    if (tid < 64) {
        double e = -(double)(2*(tid>>1)) / 64.0;
        rates[tid] = (float)pow(10000.0, e);
    }
    __syncthreads();

    int idx = blockIdx.x*blockDim.x + tid;
    // fused init (independent of feats data)
    if (idx < NN) g_cnt[idx] = 0;
    if (idx < BATCHB*HID) g_pool[idx] = 0.f;
    if (idx < BATCHB) g_bcnt[idx] = 0;
    if (idx == 0) g_rowptr[NN] = TE;

    if (idx >= NN*48) return;
    int n = idx / 48, q = idx - n*48;
    float4 v;
    if (q < 16)      v = ((const float4*)x)[(size_t)n*16 + q];
    else if (q < 32) v = ((const float4*)remb)[(size_t)rid[n]*16 + (q-16)];
    else {
        int j = (q - 32) * 4;
        float fn = (float)n;
        v.x = sinf(fn * rates[j+0]);
        v.y = cosf(fn * rates[j+1]);
        v.z = sinf(fn * rates[j+2]);
        v.w = cosf(fn * rates[j+3]);
    }
    ((float4*)g_hp)[(size_t)n*48 + q] = v;
}

// ---------------- CSR build (dst-major) ----------------
__global__ void count_kernel(const int* __restrict__ ei) {
    int i = blockIdx.x*blockDim.x + threadIdx.x;
    if (i >= TE) return;
    int dst = (i < NE) ? ei[NE + i] : (i - NE);
    atomicAdd(&g_cnt[dst], 1);
}

__global__ void scan1_kernel() {
    __shared__ int s[256];
    int tid = threadIdx.x;
    int i = blockIdx.x*256 + tid;
    int v = (i < NN) ? g_cnt[i] : 0;
    s[tid] = v; __syncthreads();
    #pragma unroll
    for (int off = 1; off < 256; off <<= 1) {
        int t = (tid >= off) ? s[tid-off] : 0;
        __syncthreads();
        s[tid] += t;
        __syncthreads();
    }
    if (i < NN) g_rowptr[i] = s[tid] - v;
    if (tid == 255) g_part[blockIdx.x] = s[255];
}

__global__ void scan2_kernel(int nb) {
    __shared__ int s[256];
    int tid = threadIdx.x;
    int v = (tid < nb) ? g_part[tid] : 0;
    s[tid] = v; __syncthreads();
    #pragma unroll
    for (int off = 1; off < 256; off <<= 1) {
        int t = (tid >= off) ? s[tid-off] : 0;
        __syncthreads();
        s[tid] += t;
        __syncthreads();
    }
    if (tid < nb) g_part[tid] = s[tid] - v;
}

__global__ void scan3_kernel() {
    int i = blockIdx.x*blockDim.x + threadIdx.x;
    if (i < NN) {
        int r = g_rowptr[i] + g_part[blockIdx.x];
        g_rowptr[i] = r;
        g_cur[i] = r;
    }
}

__global__ void fill_kernel(const int* __restrict__ ei) {
    int i = blockIdx.x*blockDim.x + threadIdx.x;
    if (i >= TE) return;
    int src, dst;
    if (i < NE) { src = ei[i]; dst = ei[NE+i]; }
    else        { src = dst = i - NE; }
    int pos = atomicAdd(&g_cur[dst], 1);
    g_col[pos] = src;
}

// ---------------- GEMM: C[M,256] = A[M,K] @ W[K,256] (+bias) + fused scores ----------------
__device__ __forceinline__ void ffma2(unsigned long long& d,
                                      unsigned long long a,
                                      unsigned long long b) {
    asm volatile("fma.rn.f32x2 %0, %1, %2, %0;" : "+l"(d) : "l"(a), "l"(b));
}
__device__ __forceinline__ void cp16(void* smem_dst, const void* gsrc, int src_bytes) {
    unsigned saddr = (unsigned)__cvta_generic_to_shared(smem_dst);
    asm volatile("cp.async.cg.shared.global [%0], [%1], 16, %2;"
                 :: "r"(saddr), "l"(gsrc), "r"(src_bytes));
}
__device__ __forceinline__ void cp_commit() { asm volatile("cp.async.commit_group;"); }
__device__ __forceinline__ void cp_wait1()  { asm volatile("cp.async.wait_group 1;"); }
__device__ __forceinline__ void cp_wait0()  { asm volatile("cp.async.wait_group 0;"); }

// BM=128 BN=128 BK=16, 256 threads, 8x8 microtile, FFMA2, 3-stage pipeline, 1 barrier/tile.
// Thread's 8 columns: {tx*4..+3} and {64+tx*4..+3} -> conflict-free B LDS.128. (R12 winner.)
__global__ __launch_bounds__(256, 2) void gemm_kernel(const float* __restrict__ W,
                                                      const float* __restrict__ bias,
                                                      const float* __restrict__ asrc,
                                                      const float* __restrict__ adst,
                                                      int M, int K, int a_is_h) {
    const float* __restrict__ A = a_is_h ? g_h : g_hp;
    float* __restrict__ C       = a_is_h ? g_hp : g_h;

    __shared__ float As[3][128][16];
    __shared__ float Bs[3][16][128];

    int tid = threadIdx.x;
    int bm = blockIdx.x * 128;
    int bn = blockIdx.y * 128;
    int tx = tid & 15;
    int ty = tid >> 4;

    unsigned long long acc[8][4];
    #pragma unroll
    for (int i = 0; i < 8; i++)
        #pragma unroll
        for (int j = 0; j < 4; j++) acc[i][j] = 0ull;

    int a_r = tid >> 2;
    int a_c = (tid & 3) * 4;
    int b_k = tid >> 4;
    int b_c = (tid & 15) * 4;

    int nk = K >> 4;

    #pragma unroll
    for (int st = 0; st < 2; st++) {
        int k0 = st << 4;
        #pragma unroll
        for (int r = 0; r < 2; r++) {
            int row = a_r + r*64;
            int grow = bm + row;
            const float* p = (grow < M) ? (A + (size_t)grow*K + k0 + a_c) : A;
            cp16(&As[st][row][a_c], p, (grow < M) ? 16 : 0);
        }
        #pragma unroll
        for (int r = 0; r < 2; r++) {
            int col = b_c + r*64;
            cp16(&Bs[st][b_k][col], W + (size_t)(k0 + b_k)*HID + bn + col, 16);
        }
        cp_commit();
    }

    int cur = 0, nxt = 2;
    for (int it = 0; it < nk; ++it) {
        if (it + 1 < nk) cp_wait1(); else cp_wait0();
        __syncthreads();

        if (it + 2 < nk) {
            int k0 = (it + 2) << 4;
            #pragma unroll
            for (int r = 0; r < 2; r++) {
                int row = a_r + r*64;
                int grow = bm + row;
                const float* p = (grow < M) ? (A + (size_t)grow*K + k0 + a_c) : A;
                cp16(&As[nxt][row][a_c], p, (grow < M) ? 16 : 0);
            }
            #pragma unroll
            for (int r = 0; r < 2; r++) {
                int col = b_c + r*64;
                cp16(&Bs[nxt][b_k][col], W + (size_t)(k0 + b_k)*HID + bn + col, 16);
            }
            cp_commit();
        }

        #pragma unroll
        for (int kq = 0; kq < 16; kq += 4) {
            float4 a4[8];
            #pragma unroll
            for (int i = 0; i < 8; i++)
                a4[i] = *(const float4*)(&As[cur][ty*8+i][kq]);
            #pragma unroll
            for (int kk = 0; kk < 4; ++kk) {
                ulonglong2 bA = *(const ulonglong2*)(&Bs[cur][kq+kk][tx*4]);
                ulonglong2 bB = *(const ulonglong2*)(&Bs[cur][kq+kk][64 + tx*4]);
                #pragma unroll
                for (int i = 0; i < 8; i++) {
                    float a = (kk == 0) ? a4[i].x : (kk == 1) ? a4[i].y
                            : (kk == 2) ? a4[i].z : a4[i].w;
                    unsigned long long a2;
                    asm("mov.b64 %0, {%1, %1};" : "=l"(a2) : "f"(a));
                    ffma2(acc[i][0], a2, bA.x);
                    ffma2(acc[i][1], a2, bA.y);
                    ffma2(acc[i][2], a2, bB.x);
                    ffma2(acc[i][3], a2, bB.y);
                }
            }
        }
        cur = (cur == 2) ? 0 : cur + 1;
        nxt = (nxt == 2) ? 0 : nxt + 1;
    }

    float cv[8][8];
    #pragma unroll
    for (int i = 0; i < 8; i++) {
        float2 p0 = *(float2*)&acc[i][0];
        float2 p1 = *(float2*)&acc[i][1];
        float2 p2 = *(float2*)&acc[i][2];
        float2 p3 = *(float2*)&acc[i][3];
        cv[i][0]=p0.x; cv[i][1]=p0.y; cv[i][2]=p1.x; cv[i][3]=p1.y;
        cv[i][4]=p2.x; cv[i][5]=p2.y; cv[i][6]=p3.x; cv[i][7]=p3.y;
    }
    int c0 = bn + tx*4;
    int c1 = bn + 64 + tx*4;
    if (bias) {
        float4 t0 = *(const float4*)(bias + c0);
        float4 t1 = *(const float4*)(bias + c1);
        #pragma unroll
        for (int i = 0; i < 8; i++) {
            cv[i][0]+=t0.x; cv[i][1]+=t0.y; cv[i][2]+=t0.z; cv[i][3]+=t0.w;
            cv[i][4]+=t1.x; cv[i][5]+=t1.y; cv[i][6]+=t1.z; cv[i][7]+=t1.w;
        }
    }
    #pragma unroll
    for (int i = 0; i < 8; i++) {
        int row = bm + ty*8 + i;
        if (row < M) {
            *(float4*)(C + (size_t)row*HID + c0) = make_float4(cv[i][0],cv[i][1],cv[i][2],cv[i][3]);
            *(float4*)(C + (size_t)row*HID + c1) = make_float4(cv[i][4],cv[i][5],cv[i][6],cv[i][7]);
        }
    }

    if (asrc) {
        int head0 = bn >> 6;
        int head1 = head0 + 1;
        float av0[4], av1[4], dv0[4], dv1[4];
        #pragma unroll
        for (int j = 0; j < 4; j++) {
            av0[j] = asrc[head0*64 + tx*4 + j];
            av1[j] = asrc[head1*64 + tx*4 + j];
            dv0[j] = adst[head0*64 + tx*4 + j];
            dv1[j] = adst[head1*64 + tx*4 + j];
        }
        #pragma unroll
        for (int i = 0; i < 8; i++) {
            float ps0 = 0.f, pd0 = 0.f, ps1 = 0.f, pd1 = 0.f;
            #pragma unroll
            for (int j = 0; j < 4; j++) {
                ps0 += cv[i][j]   * av0[j];
                pd0 += cv[i][j]   * dv0[j];
                ps1 += cv[i][4+j] * av1[j];
                pd1 += cv[i][4+j] * dv1[j];
            }
            #pragma unroll
            for (int off = 8; off; off >>= 1) {
                ps0 += __shfl_xor_sync(0xffffffffu, ps0, off, 16);
                pd0 += __shfl_xor_sync(0xffffffffu, pd0, off, 16);
                ps1 += __shfl_xor_sync(0xffffffffu, ps1, off, 16);
                pd1 += __shfl_xor_sync(0xffffffffu, pd1, off, 16);
            }
            int row = bm + ty*8 + i;
            if (tx == 0 && row < M) {
                g_ssrc[(size_t)row*4 + head0] = ps0;
                g_ssrc[(size_t)row*4 + head1] = ps1;
                g_sdst[(size_t)row*4 + head0] = pd0;
                g_sdst[(size_t)row*4 + head1] = pd1;
            }
        }
    }
}

// ---------------- aggregation + bias + relu + layernorm: one warp per dst (R12) ----------------
__global__ void aggregate_kernel(const float* __restrict__ bias,
                                 const float* __restrict__ lng,
                                 const float* __restrict__ lnb) {
    int warp = (blockIdx.x*blockDim.x + threadIdx.x) >> 5;
    int lane = threadIdx.x & 31;
    if (warp >= NN) return;
    int n = warp;
    int start = g_rowptr[n], end = g_rowptr[n+1];

    float4 sd4 = *(const float4*)(g_sdst + (size_t)n*4);
    bool lo = (lane < 16);
    float sdh0 = lo ? sd4.x : sd4.y;
    float sdh1 = lo ? sd4.z : sd4.w;

    float ax = 0.f, ay = 0.f, az = 0.f, aw = 0.f;
    float bx = 0.f, by = 0.f, bz2 = 0.f, bw = 0.f;
    float den0 = 0.f, den1 = 0.f;
    for (int i = start; i < end; ++i) {
        int s = g_col[i];
        float4 ss = *(const float4*)(g_ssrc + (size_t)s*4);
        float e0 = (lo ? ss.x : ss.y) + sdh0; e0 = e0 > 0.f ? e0 : 0.2f*e0;
        float e1 = (lo ? ss.z : ss.w) + sdh1; e1 = e1 > 0.f ? e1 : 0.2f*e1;
        float w0 = __expf(e0);
        float w1 = __expf(e1);
        den0 += w0; den1 += w1;
        const float4* row = (const float4*)(g_hp + (size_t)s*HID);
        float4 v0 = row[lane], v1 = row[lane+32];
        ax += w0*v0.x; ay += w0*v0.y; az += w0*v0.z; aw += w0*v0.w;
        bx += w1*v1.x; by += w1*v1.y; bz2 += w1*v1.z; bw += w1*v1.w;
    }
    float inv0 = 1.f/den0, inv1 = 1.f/den1;

    int c0 = lane*4, c1 = 128 + lane*4;
    float4 bb0 = *(const float4*)(bias + c0);
    float4 bb1 = *(const float4*)(bias + c1);
    float vals[8];
    vals[0] = fmaxf(0.f, ax*inv0 + bb0.x);
    vals[1] = fmaxf(0.f, ay*inv0 + bb0.y);
    vals[2] = fmaxf(0.f, az*inv0 + bb0.z);
    vals[3] = fmaxf(0.f, aw*inv0 + bb0.w);
    vals[4] = fmaxf(0.f, bx*inv1 + bb1.x);
    vals[5] = fmaxf(0.f, by*inv1 + bb1.y);
    vals[6] = fmaxf(0.f, bz2*inv1 + bb1.z);
    vals[7] = fmaxf(0.f, bw*inv1 + bb1.w);

    float lsum = 0.f;
    #pragma unroll
    for (int j = 0; j < 8; j++) lsum += vals[j];
    #pragma unroll
    for (int off = 16; off; off >>= 1) lsum += __shfl_xor_sync(0xffffffffu, lsum, off);
    float mu = lsum * (1.f/256.f);
    float lsq = 0.f;
    #pragma unroll
    for (int j = 0; j < 8; j++) { float d = vals[j]-mu; lsq += d*d; }
    #pragma unroll
    for (int off = 16; off; off >>= 1) lsq += __shfl_xor_sync(0xffffffffu, lsq, off);
    float rstd = rsqrtf(lsq * (1.f/256.f) + 1e-5f);

    float4 gg0 = *(const float4*)(lng + c0);
    float4 gg1 = *(const float4*)(lng + c1);
    float4 lb0 = *(const float4*)(lnb + c0);
    float4 lb1 = *(const float4*)(lnb + c1);
    float4 o0, o1;
    o0.x = (vals[0]-mu)*rstd*gg0.x + lb0.x;
    o0.y = (vals[1]-mu)*rstd*gg0.y + lb0.y;
    o0.z = (vals[2]-mu)*rstd*gg0.z + lb0.z;
    o0.w = (vals[3]-mu)*rstd*gg0.w + lb0.w;
    o1.x = (vals[4]-mu)*rstd*gg1.x + lb1.x;
    o1.y = (vals[5]-mu)*rstd*gg1.y + lb1.y;
    o1.z = (vals[6]-mu)*rstd*gg1.z + lb1.z;
    o1.w = (vals[7]-mu)*rstd*gg1.w + lb1.w;
    *(float4*)(g_h + (size_t)n*HID + c0) = o0;
    *(float4*)(g_h + (size_t)n*HID + c1) = o1;
}

// ---------------- pooling ----------------
__global__ void pool_kernel(const int* __restrict__ batch) {
    int gw = (blockIdx.x*blockDim.x + threadIdx.x) >> 5;
    int lane = threadIdx.x & 31;
    int n0 = gw * 32;
    if (n0 >= NN) return;
    int nend = n0 + 32; if (nend > NN) nend = NN;

    float4 a0 = make_float4(0,0,0,0), a1 = make_float4(0,0,0,0);
    int curb = batch[n0];
    int cnt = 0;
    for (int n = n0; n < nend; ++n) {
        int b = batch[n];
        if (b != curb) {
            atomicAdd(&g_pool[curb*HID + lane*4+0], a0.x);
            atomicAdd(&g_pool[curb*HID + lane*4+1], a0.y);
            atomicAdd(&g_pool[curb*HID + lane*4+2], a0.z);
            atomicAdd(&g_pool[curb*HID + lane*4+3], a0.w);
            atomicAdd(&g_pool[curb*HID + 128 + lane*4+0], a1.x);
            atomicAdd(&g_pool[curb*HID + 128 + lane*4+1], a1.y);
            atomicAdd(&g_pool[curb*HID + 128 + lane*4+2], a1.z);
            atomicAdd(&g_pool[curb*HID + 128 + lane*4+3], a1.w);
            if (lane == 0) atomicAdd(&g_bcnt[curb], cnt);
            a0 = make_float4(0,0,0,0); a1 = make_float4(0,0,0,0);
            cnt = 0; curb = b;
        }
        const float4* row = (const float4*)(g_h + (size_t)n*HID);
        float4 v0 = row[lane], v1 = row[lane+32];
        a0.x += v0.x; a0.y += v0.y; a0.z += v0.z; a0.w += v0.w;
        a1.x += v1.x; a1.y += v1.y; a1.z += v1.z; a1.w += v1.w;
        cnt++;
    }
    atomicAdd(&g_pool[curb*HID + lane*4+0], a0.x);
    atomicAdd(&g_pool[curb*HID + lane*4+1], a0.y);
    atomicAdd(&g_pool[curb*HID + lane*4+2], a0.z);
    atomicAdd(&g_pool[curb*HID + lane*4+3], a0.w);
    atomicAdd(&g_pool[curb*HID + 128 + lane*4+0], a1.x);
    atomicAdd(&g_pool[curb*HID + 128 + lane*4+1], a1.y);
    atomicAdd(&g_pool[curb*HID + 128 + lane*4+2], a1.z);
    atomicAdd(&g_pool[curb*HID + 128 + lane*4+3], a1.w);
    if (lane == 0) atomicAdd(&g_bcnt[curb], cnt);
}

// ---------------- readout head ----------------
__global__ __launch_bounds__(256) void head_kernel(const float* __restrict__ w1,
                                                   const float* __restrict__ b1,
                                                   const float* __restrict__ w2,
                                                   const float* __restrict__ b2,
                                                   float* __restrict__ out) {
    __shared__ float p[BATCHB*HID];
    __shared__ float t[BATCHB*HID];
    int tid = threadIdx.x;
    for (int i = tid; i < BATCHB*HID; i += 256) {
        float c = fmaxf((float)g_bcnt[i / HID], 1.f);
        p[i] = g_pool[i] / c;
    }
    __syncthreads();
    {
        float acc[BATCHB];
        #pragma unroll
        for (int b = 0; b < BATCHB; b++) acc[b] = 0.f;
        for (int k = 0; k < HID; k++) {
            float w = w1[k*HID + tid];
            #pragma unroll
            for (int b = 0; b < BATCHB; b++) acc[b] += p[b*HID + k] * w;
        }
        #pragma unroll
        for (int b = 0; b < BATCHB; b++) {
            float v = acc[b] + b1[tid];
            t[b*HID + tid] = 0.5f * v * (1.f + erff(v * 0.70710678118654752f));
        }
    }
    __syncthreads();
    {
        float acc[BATCHB];
        #pragma unroll
        for (int b = 0; b < BATCHB; b++) acc[b] = 0.f;
        for (int k = 0; k < HID; k++) {
            float w = w2[k*HID + tid];
            #pragma unroll
            for (int b = 0; b < BATCHB; b++) acc[b] += t[b*HID + k] * w;
        }
        #pragma unroll
        for (int b = 0; b < BATCHB; b++) out[b*HID + tid] = acc[b] + b2[tid];
    }
}

// ---------------- launch ----------------
extern "C" void kernel_launch(void* const* d_in, const int* in_sizes, int n_in,
                              void* d_out, int out_size) {
    const float* x       = (const float*)d_in[0];
    const float* remb    = (const float*)d_in[1];
    const float* in_w    = (const float*)d_in[2];
    const float* in_b    = (const float*)d_in[3];
    const float* gat_w   = (const float*)d_in[4];
    const float* att_src = (const float*)d_in[5];
    const float* att_dst = (const float*)d_in[6];
    const float* gat_b   = (const float*)d_in[7];
    const float* ln_g    = (const float*)d_in[8];
    const float* ln_b    = (const float*)d_in[9];
    const float* ro_w1   = (const float*)d_in[10];
    const float* ro_b1   = (const float*)d_in[11];
    const float* ro_w2   = (const float*)d_in[12];
    const float* ro_b2   = (const float*)d_in[13];
    const int*   ei      = (const int*)d_in[14];
    const int*   batch   = (const int*)d_in[15];
    const int*   rid     = (const int*)d_in[16];
    float* out = (float*)d_out;

    dim3 gemm_grid((NN + 127)/128, HID/128);

    feats_kernel<<<(NN*48 + 255)/256, 256>>>(x, remb, rid);                       // 0 (rates+zero fused)
    gemm_kernel<<<gemm_grid, 256>>>(in_w, in_b, nullptr, nullptr, NN, 192, 0);    // 1
    gemm_kernel<<<gemm_grid, 256>>>(gat_w, nullptr, att_src, att_dst, NN, HID, 1);// 2
    count_kernel<<<(TE + 255)/256, 256>>>(ei);                                    // 3
    scan1_kernel<<<196, 256>>>();                                                 // 4
    scan2_kernel<<<1, 256>>>(196);                                                // 5
    scan3_kernel<<<196, 256>>>();                                                 // 6
    fill_kernel<<<(TE + 255)/256, 256>>>(ei);                                     // 7
    aggregate_kernel<<<NN/8, 256>>>(gat_b, ln_g, ln_b);                           // 8

    for (int l = 1; l < 4; ++l) {
        gemm_kernel<<<gemm_grid, 256>>>(gat_w + (size_t)l*HID*HID, nullptr,
                                        att_src + l*256, att_dst + l*256, NN, HID, 1);
        aggregate_kernel<<<NN/8, 256>>>(gat_b + l*HID, ln_g + l*HID, ln_b + l*HID);
    }

    pool_kernel<<<196, 256>>>(batch);
    head_kernel<<<1, 256>>>(ro_w1, ro_b1, ro_w2, ro_b2, out);
}

// round 17
// speedup vs baseline: 1.6436x; 1.6436x over previous
#include <cuda_runtime.h>
#include <math.h>

#define NN 50000
#define NE 400000
#define TE 450000         // NE + NN self loops
#define HID 256
#define BATCHB 16

// ---------------- scratch ----------------
__device__ float g_h [(size_t)NN*HID];   // layer input / LN output
__device__ float g_hp[(size_t)NN*HID];   // h @ W (also feats buffer, N*192 < N*256)
__device__ float g_ssrc[NN*4];
__device__ float g_sdst[NN*4];
__device__ int   g_cnt[NN];
__device__ int   g_rowptr[NN+1];
__device__ int   g_cur[NN];
__device__ int   g_col[TE];
__device__ int   g_part[256];
__device__ float g_pool[BATCHB*HID];
__device__ int   g_bcnt[BATCHB];
__device__ float g_rates[64];

// ---------------- init ----------------
__global__ void zero_kernel() {
    int i = blockIdx.x*blockDim.x + threadIdx.x;
    if (i < NN) g_cnt[i] = 0;
    if (i < BATCHB*HID) g_pool[i] = 0.f;
    if (i < BATCHB) g_bcnt[i] = 0;
    if (i == 0) g_rowptr[NN] = TE;
}

__global__ void rates_kernel() {
    int j = threadIdx.x;
    if (j < 64) {
        double e = -(double)(2*(j>>1)) / 64.0;
        g_rates[j] = (float)pow(10000.0, e);
    }
}

// feats = [x | region_emb[rid] | posenc]  -> g_hp as [N,192], float4 granularity
__global__ void feats_kernel(const float* __restrict__ x,
                             const float* __restrict__ remb,
                             const int*   __restrict__ rid) {
    int idx = blockIdx.x*blockDim.x + threadIdx.x;
    if (idx >= NN*48) return;
    int n = idx / 48, q = idx - n*48;
    float4 v;
    if (q < 16)      v = ((const float4*)x)[(size_t)n*16 + q];
    else if (q < 32) v = ((const float4*)remb)[(size_t)rid[n]*16 + (q-16)];
    else {
        int j = (q - 32) * 4;
        float fn = (float)n;
        v.x = sinf(fn * g_rates[j+0]);
        v.y = cosf(fn * g_rates[j+1]);
        v.z = sinf(fn * g_rates[j+2]);
        v.w = cosf(fn * g_rates[j+3]);
    }
    ((float4*)g_hp)[(size_t)n*48 + q] = v;
}

// ---------------- CSR build (dst-major) ----------------
__global__ void count_kernel(const int* __restrict__ ei) {
    int i = blockIdx.x*blockDim.x + threadIdx.x;
    if (i >= TE) return;
    int dst = (i < NE) ? ei[NE + i] : (i - NE);
    atomicAdd(&g_cnt[dst], 1);
}

__global__ void scan1_kernel() {
    __shared__ int s[256];
    int tid = threadIdx.x;
    int i = blockIdx.x*256 + tid;
    int v = (i < NN) ? g_cnt[i] : 0;
    s[tid] = v; __syncthreads();
    #pragma unroll
    for (int off = 1; off < 256; off <<= 1) {
        int t = (tid >= off) ? s[tid-off] : 0;
        __syncthreads();
        s[tid] += t;
        __syncthreads();
    }
    if (i < NN) g_rowptr[i] = s[tid] - v;
    if (tid == 255) g_part[blockIdx.x] = s[255];
}

__global__ void scan2_kernel(int nb) {
    __shared__ int s[256];
    int tid = threadIdx.x;
    int v = (tid < nb) ? g_part[tid] : 0;
    s[tid] = v; __syncthreads();
    #pragma unroll
    for (int off = 1; off < 256; off <<= 1) {
        int t = (tid >= off) ? s[tid-off] : 0;
        __syncthreads();
        s[tid] += t;
        __syncthreads();
    }
    if (tid < nb) g_part[tid] = s[tid] - v;
}

__global__ void scan3_kernel() {
    int i = blockIdx.x*blockDim.x + threadIdx.x;
    if (i < NN) {
        int r = g_rowptr[i] + g_part[blockIdx.x];
        g_rowptr[i] = r;
        g_cur[i] = r;
    }
}

__global__ void fill_kernel(const int* __restrict__ ei) {
    int i = blockIdx.x*blockDim.x + threadIdx.x;
    if (i >= TE) return;
    int src, dst;
    if (i < NE) { src = ei[i]; dst = ei[NE+i]; }
    else        { src = dst = i - NE; }
    int pos = atomicAdd(&g_cur[dst], 1);
    g_col[pos] = src;
}

// ---------------- GEMM: C[M,256] = A[M,K] @ W[K,256] (+bias) + fused scores ----------------
__device__ __forceinline__ void ffma2(unsigned long long& d,
                                      unsigned long long a,
                                      unsigned long long b) {
    asm volatile("fma.rn.f32x2 %0, %1, %2, %0;" : "+l"(d) : "l"(a), "l"(b));
}
__device__ __forceinline__ void cp16(void* smem_dst, const void* gsrc, int src_bytes) {
    unsigned saddr = (unsigned)__cvta_generic_to_shared(smem_dst);
    asm volatile("cp.async.cg.shared.global [%0], [%1], 16, %2;"
                 :: "r"(saddr), "l"(gsrc), "r"(src_bytes));
}
__device__ __forceinline__ void cp_commit() { asm volatile("cp.async.commit_group;"); }
__device__ __forceinline__ void cp_wait1()  { asm volatile("cp.async.wait_group 1;"); }
__device__ __forceinline__ void cp_wait0()  { asm volatile("cp.async.wait_group 0;"); }

// BM=128 BN=128 BK=16, 256 threads, 8x8 microtile, FFMA2, 3-stage pipeline, 1 barrier/tile.
// Thread's 8 columns: {tx*4..+3} and {64+tx*4..+3} -> conflict-free B LDS.128.
__global__ __launch_bounds__(256, 2) void gemm_kernel(const float* __restrict__ W,
                                                      const float* __restrict__ bias,
                                                      const float* __restrict__ asrc,
                                                      const float* __restrict__ adst,
                                                      int M, int K, int a_is_h) {
    const float* __restrict__ A = a_is_h ? g_h : g_hp;
    float* __restrict__ C       = a_is_h ? g_hp : g_h;

    __shared__ float As[3][128][16];
    __shared__ float Bs[3][16][128];

    int tid = threadIdx.x;
    int bm = blockIdx.x * 128;
    int bn = blockIdx.y * 128;
    int tx = tid & 15;
    int ty = tid >> 4;

    unsigned long long acc[8][4];
    #pragma unroll
    for (int i = 0; i < 8; i++)
        #pragma unroll
        for (int j = 0; j < 4; j++) acc[i][j] = 0ull;

    int a_r = tid >> 2;
    int a_c = (tid & 3) * 4;
    int b_k = tid >> 4;
    int b_c = (tid & 15) * 4;

    int nk = K >> 4;

    #pragma unroll
    for (int st = 0; st < 2; st++) {
        int k0 = st << 4;
        #pragma unroll
        for (int r = 0; r < 2; r++) {
            int row = a_r + r*64;
            int grow = bm + row;
            const float* p = (grow < M) ? (A + (size_t)grow*K + k0 + a_c) : A;
            cp16(&As[st][row][a_c], p, (grow < M) ? 16 : 0);
        }
        #pragma unroll
        for (int r = 0; r < 2; r++) {
            int col = b_c + r*64;
            cp16(&Bs[st][b_k][col], W + (size_t)(k0 + b_k)*HID + bn + col, 16);
        }
        cp_commit();
    }

    int cur = 0, nxt = 2;
    for (int it = 0; it < nk; ++it) {
        if (it + 1 < nk) cp_wait1(); else cp_wait0();
        __syncthreads();

        if (it + 2 < nk) {
            int k0 = (it + 2) << 4;
            #pragma unroll
            for (int r = 0; r < 2; r++) {
                int row = a_r + r*64;
                int grow = bm + row;
                const float* p = (grow < M) ? (A + (size_t)grow*K + k0 + a_c) : A;
                cp16(&As[nxt][row][a_c], p, (grow < M) ? 16 : 0);
            }
            #pragma unroll
            for (int r = 0; r < 2; r++) {
                int col = b_c + r*64;
                cp16(&Bs[nxt][b_k][col], W + (size_t)(k0 + b_k)*HID + bn + col, 16);
            }
            cp_commit();
        }

        #pragma unroll
        for (int kq = 0; kq < 16; kq += 4) {
            float4 a4[8];
            #pragma unroll
            for (int i = 0; i < 8; i++)
                a4[i] = *(const float4*)(&As[cur][ty*8+i][kq]);
            #pragma unroll
            for (int kk = 0; kk < 4; ++kk) {
                ulonglong2 bA = *(const ulonglong2*)(&Bs[cur][kq+kk][tx*4]);
                ulonglong2 bB = *(const ulonglong2*)(&Bs[cur][kq+kk][64 + tx*4]);
                #pragma unroll
                for (int i = 0; i < 8; i++) {
                    float a = (kk == 0) ? a4[i].x : (kk == 1) ? a4[i].y
                            : (kk == 2) ? a4[i].z : a4[i].w;
                    unsigned long long a2;
                    asm("mov.b64 %0, {%1, %1};" : "=l"(a2) : "f"(a));
                    ffma2(acc[i][0], a2, bA.x);
                    ffma2(acc[i][1], a2, bA.y);
                    ffma2(acc[i][2], a2, bB.x);
                    ffma2(acc[i][3], a2, bB.y);
                }
            }
        }
        cur = (cur == 2) ? 0 : cur + 1;
        nxt = (nxt == 2) ? 0 : nxt + 1;
    }

    float cv[8][8];
    #pragma unroll
    for (int i = 0; i < 8; i++) {
        float2 p0 = *(float2*)&acc[i][0];
        float2 p1 = *(float2*)&acc[i][1];
        float2 p2 = *(float2*)&acc[i][2];
        float2 p3 = *(float2*)&acc[i][3];
        cv[i][0]=p0.x; cv[i][1]=p0.y; cv[i][2]=p1.x; cv[i][3]=p1.y;
        cv[i][4]=p2.x; cv[i][5]=p2.y; cv[i][6]=p3.x; cv[i][7]=p3.y;
    }
    int c0 = bn + tx*4;
    int c1 = bn + 64 + tx*4;
    if (bias) {
        float4 t0 = *(const float4*)(bias + c0);
        float4 t1 = *(const float4*)(bias + c1);
        #pragma unroll
        for (int i = 0; i < 8; i++) {
            cv[i][0]+=t0.x; cv[i][1]+=t0.y; cv[i][2]+=t0.z; cv[i][3]+=t0.w;
            cv[i][4]+=t1.x; cv[i][5]+=t1.y; cv[i][6]+=t1.z; cv[i][7]+=t1.w;
        }
    }
    #pragma unroll
    for (int i = 0; i < 8; i++) {
        int row = bm + ty*8 + i;
        if (row < M) {
            *(float4*)(C + (size_t)row*HID + c0) = make_float4(cv[i][0],cv[i][1],cv[i][2],cv[i][3]);
            *(float4*)(C + (size_t)row*HID + c1) = make_float4(cv[i][4],cv[i][5],cv[i][6],cv[i][7]);
        }
    }

    // fused scores: head0 = bn/64 (cols 0..63 of bn half), head1 = head0+1
    if (asrc) {
        int head0 = bn >> 6;
        int head1 = head0 + 1;
        float av0[4], av1[4], dv0[4], dv1[4];
        #pragma unroll
        for (int j = 0; j < 4; j++) {
            av0[j] = asrc[head0*64 + tx*4 + j];
            av1[j] = asrc[head1*64 + tx*4 + j];
            dv0[j] = adst[head0*64 + tx*4 + j];
            dv1[j] = adst[head1*64 + tx*4 + j];
        }
        #pragma unroll
        for (int i = 0; i < 8; i++) {
            float ps0 = 0.f, pd0 = 0.f, ps1 = 0.f, pd1 = 0.f;
            #pragma unroll
            for (int j = 0; j < 4; j++) {
                ps0 += cv[i][j]   * av0[j];
                pd0 += cv[i][j]   * dv0[j];
                ps1 += cv[i][4+j] * av1[j];
                pd1 += cv[i][4+j] * dv1[j];
            }
            #pragma unroll
            for (int off = 8; off; off >>= 1) {
                ps0 += __shfl_xor_sync(0xffffffffu, ps0, off, 16);
                pd0 += __shfl_xor_sync(0xffffffffu, pd0, off, 16);
                ps1 += __shfl_xor_sync(0xffffffffu, ps1, off, 16);
                pd1 += __shfl_xor_sync(0xffffffffu, pd1, off, 16);
            }
            int row = bm + ty*8 + i;
            if (tx == 0 && row < M) {
                g_ssrc[(size_t)row*4 + head0] = ps0;
                g_ssrc[(size_t)row*4 + head1] = ps1;
                g_sdst[(size_t)row*4 + head0] = pd0;
                g_sdst[(size_t)row*4 + head1] = pd1;
            }
        }
    }
}

// ---------------- aggregation + bias + relu + layernorm: one warp per dst ----------------
// Single pass (scores bounded; softmax shift-invariant -> no max pass).
__global__ void aggregate_kernel(const float* __restrict__ bias,
                                 const float* __restrict__ lng,
                                 const float* __restrict__ lnb) {
    int warp = (blockIdx.x*blockDim.x + threadIdx.x) >> 5;
    int lane = threadIdx.x & 31;
    if (warp >= NN) return;
    int n = warp;
    int start = g_rowptr[n], end = g_rowptr[n+1];

    float4 sd4 = *(const float4*)(g_sdst + (size_t)n*4);
    bool lo = (lane < 16);
    float sdh0 = lo ? sd4.x : sd4.y;
    float sdh1 = lo ? sd4.z : sd4.w;

    float ax = 0.f, ay = 0.f, az = 0.f, aw = 0.f;
    float bx = 0.f, by = 0.f, bz2 = 0.f, bw = 0.f;
    float den0 = 0.f, den1 = 0.f;
    for (int i = start; i < end; ++i) {
        int s = g_col[i];
        float4 ss = *(const float4*)(g_ssrc + (size_t)s*4);
        float e0 = (lo ? ss.x : ss.y) + sdh0; e0 = e0 > 0.f ? e0 : 0.2f*e0;
        float e1 = (lo ? ss.z : ss.w) + sdh1; e1 = e1 > 0.f ? e1 : 0.2f*e1;
        float w0 = __expf(e0);
        float w1 = __expf(e1);
        den0 += w0; den1 += w1;
        const float4* row = (const float4*)(g_hp + (size_t)s*HID);
        float4 v0 = row[lane], v1 = row[lane+32];
        ax += w0*v0.x; ay += w0*v0.y; az += w0*v0.z; aw += w0*v0.w;
        bx += w1*v1.x; by += w1*v1.y; bz2 += w1*v1.z; bw += w1*v1.w;
    }
    float inv0 = 1.f/den0, inv1 = 1.f/den1;

    int c0 = lane*4, c1 = 128 + lane*4;
    float4 bb0 = *(const float4*)(bias + c0);
    float4 bb1 = *(const float4*)(bias + c1);
    float vals[8];
    vals[0] = fmaxf(0.f, ax*inv0 + bb0.x);
    vals[1] = fmaxf(0.f, ay*inv0 + bb0.y);
    vals[2] = fmaxf(0.f, az*inv0 + bb0.z);
    vals[3] = fmaxf(0.f, aw*inv0 + bb0.w);
    vals[4] = fmaxf(0.f, bx*inv1 + bb1.x);
    vals[5] = fmaxf(0.f, by*inv1 + bb1.y);
    vals[6] = fmaxf(0.f, bz2*inv1 + bb1.z);
    vals[7] = fmaxf(0.f, bw*inv1 + bb1.w);

    float lsum = 0.f;
    #pragma unroll
    for (int j = 0; j < 8; j++) lsum += vals[j];
    #pragma unroll
    for (int off = 16; off; off >>= 1) lsum += __shfl_xor_sync(0xffffffffu, lsum, off);
    float mu = lsum * (1.f/256.f);
    float lsq = 0.f;
    #pragma unroll
    for (int j = 0; j < 8; j++) { float d = vals[j]-mu; lsq += d*d; }
    #pragma unroll
    for (int off = 16; off; off >>= 1) lsq += __shfl_xor_sync(0xffffffffu, lsq, off);
    float rstd = rsqrtf(lsq * (1.f/256.f) + 1e-5f);

    float4 gg0 = *(const float4*)(lng + c0);
    float4 gg1 = *(const float4*)(lng + c1);
    float4 lb0 = *(const float4*)(lnb + c0);
    float4 lb1 = *(const float4*)(lnb + c1);
    float4 o0, o1;
    o0.x = (vals[0]-mu)*rstd*gg0.x + lb0.x;
    o0.y = (vals[1]-mu)*rstd*gg0.y + lb0.y;
    o0.z = (vals[2]-mu)*rstd*gg0.z + lb0.z;
    o0.w = (vals[3]-mu)*rstd*gg0.w + lb0.w;
    o1.x = (vals[4]-mu)*rstd*gg1.x + lb1.x;
    o1.y = (vals[5]-mu)*rstd*gg1.y + lb1.y;
    o1.z = (vals[6]-mu)*rstd*gg1.z + lb1.z;
    o1.w = (vals[7]-mu)*rstd*gg1.w + lb1.w;
    *(float4*)(g_h + (size_t)n*HID + c0) = o0;
    *(float4*)(g_h + (size_t)n*HID + c1) = o1;
}

// ---------------- pooling ----------------
__global__ void pool_kernel(const int* __restrict__ batch) {
    int gw = (blockIdx.x*blockDim.x + threadIdx.x) >> 5;
    int lane = threadIdx.x & 31;
    int n0 = gw * 32;
    if (n0 >= NN) return;
    int nend = n0 + 32; if (nend > NN) nend = NN;

    float4 a0 = make_float4(0,0,0,0), a1 = make_float4(0,0,0,0);
    int curb = batch[n0];
    int cnt = 0;
    for (int n = n0; n < nend; ++n) {
        int b = batch[n];
        if (b != curb) {
            atomicAdd(&g_pool[curb*HID + lane*4+0], a0.x);
            atomicAdd(&g_pool[curb*HID + lane*4+1], a0.y);
            atomicAdd(&g_pool[curb*HID + lane*4+2], a0.z);
            atomicAdd(&g_pool[curb*HID + lane*4+3], a0.w);
            atomicAdd(&g_pool[curb*HID + 128 + lane*4+0], a1.x);
            atomicAdd(&g_pool[curb*HID + 128 + lane*4+1], a1.y);
            atomicAdd(&g_pool[curb*HID + 128 + lane*4+2], a1.z);
            atomicAdd(&g_pool[curb*HID + 128 + lane*4+3], a1.w);
            if (lane == 0) atomicAdd(&g_bcnt[curb], cnt);
            a0 = make_float4(0,0,0,0); a1 = make_float4(0,0,0,0);
            cnt = 0; curb = b;
        }
        const float4* row = (const float4*)(g_h + (size_t)n*HID);
        float4 v0 = row[lane], v1 = row[lane+32];
        a0.x += v0.x; a0.y += v0.y; a0.z += v0.z; a0.w += v0.w;
        a1.x += v1.x; a1.y += v1.y; a1.z += v1.z; a1.w += v1.w;
        cnt++;
    }
    atomicAdd(&g_pool[curb*HID + lane*4+0], a0.x);
    atomicAdd(&g_pool[curb*HID + lane*4+1], a0.y);
    atomicAdd(&g_pool[curb*HID + lane*4+2], a0.z);
    atomicAdd(&g_pool[curb*HID + lane*4+3], a0.w);
    atomicAdd(&g_pool[curb*HID + 128 + lane*4+0], a1.x);
    atomicAdd(&g_pool[curb*HID + 128 + lane*4+1], a1.y);
    atomicAdd(&g_pool[curb*HID + 128 + lane*4+2], a1.z);
    atomicAdd(&g_pool[curb*HID + 128 + lane*4+3], a1.w);
    if (lane == 0) atomicAdd(&g_bcnt[curb], cnt);
}

// ---------------- readout head ----------------
__global__ __launch_bounds__(256) void head_kernel(const float* __restrict__ w1,
                                                   const float* __restrict__ b1,
                                                   const float* __restrict__ w2,
                                                   const float* __restrict__ b2,
                                                   float* __restrict__ out) {
    __shared__ float p[BATCHB*HID];
    __shared__ float t[BATCHB*HID];
    int tid = threadIdx.x;
    for (int i = tid; i < BATCHB*HID; i += 256) {
        float c = fmaxf((float)g_bcnt[i / HID], 1.f);
        p[i] = g_pool[i] / c;
    }
    __syncthreads();
    {
        float acc[BATCHB];
        #pragma unroll
        for (int b = 0; b < BATCHB; b++) acc[b] = 0.f;
        for (int k = 0; k < HID; k++) {
            float w = w1[k*HID + tid];
            #pragma unroll
            for (int b = 0; b < BATCHB; b++) acc[b] += p[b*HID + k] * w;
        }
        #pragma unroll
        for (int b = 0; b < BATCHB; b++) {
            float v = acc[b] + b1[tid];
            t[b*HID + tid] = 0.5f * v * (1.f + erff(v * 0.70710678118654752f));
        }
    }
    __syncthreads();
    {
        float acc[BATCHB];
        #pragma unroll
        for (int b = 0; b < BATCHB; b++) acc[b] = 0.f;
        for (int k = 0; k < HID; k++) {
            float w = w2[k*HID + tid];
            #pragma unroll
            for (int b = 0; b < BATCHB; b++) acc[b] += t[b*HID + k] * w;
        }
        #pragma unroll
        for (int b = 0; b < BATCHB; b++) out[b*HID + tid] = acc[b] + b2[tid];
    }
}

// ---------------- launch ----------------
extern "C" void kernel_launch(void* const* d_in, const int* in_sizes, int n_in,
                              void* d_out, int out_size) {
    const float* x       = (const float*)d_in[0];
    const float* remb    = (const float*)d_in[1];
    const float* in_w    = (const float*)d_in[2];
    const float* in_b    = (const float*)d_in[3];
    const float* gat_w   = (const float*)d_in[4];
    const float* att_src = (const float*)d_in[5];
    const float* att_dst = (const float*)d_in[6];
    const float* gat_b   = (const float*)d_in[7];
    const float* ln_g    = (const float*)d_in[8];
    const float* ln_b    = (const float*)d_in[9];
    const float* ro_w1   = (const float*)d_in[10];
    const float* ro_b1   = (const float*)d_in[11];
    const float* ro_w2   = (const float*)d_in[12];
    const float* ro_b2   = (const float*)d_in[13];
    const int*   ei      = (const int*)d_in[14];
    const int*   batch   = (const int*)d_in[15];
    const int*   rid     = (const int*)d_in[16];
    float* out = (float*)d_out;

    dim3 gemm_grid((NN + 127)/128, HID/128);

    rates_kernel<<<1, 64>>>();                                                    // 0
    feats_kernel<<<(NN*48 + 255)/256, 256>>>(x, remb, rid);                       // 1
    gemm_kernel<<<gemm_grid, 256>>>(in_w, in_b, nullptr, nullptr, NN, 192, 0);    // 2
    gemm_kernel<<<gemm_grid, 256>>>(gat_w, nullptr, att_src, att_dst, NN, HID, 1);// 3
    zero_kernel<<<196, 256>>>();                                                  // 4
    count_kernel<<<(TE + 255)/256, 256>>>(ei);                                    // 5
    scan1_kernel<<<196, 256>>>();                                                 // 6
    scan2_kernel<<<1, 256>>>(196);                                                // 7
    scan3_kernel<<<196, 256>>>();                                                 // 8
    fill_kernel<<<(TE + 255)/256, 256>>>(ei);                                     // 9
    aggregate_kernel<<<NN/8, 256>>>(gat_b, ln_g, ln_b);                           // 10

    for (int l = 1; l < 4; ++l) {
        gemm_kernel<<<gemm_grid, 256>>>(gat_w + (size_t)l*HID*HID, nullptr,
                                        att_src + l*256, att_dst + l*256, NN, HID, 1);
        aggregate_kernel<<<NN/8, 256>>>(gat_b + l*HID, ln_g + l*HID, ln_b + l*HID);
    }

    pool_kernel<<<196, 256>>>(batch);
    head_kernel<<<1, 256>>>(ro_w1, ro_b1, ro_w2, ro_b2, out);
}